// round 16
// baseline (speedup 1.0000x reference)
#include <cuda_runtime.h>
#include <cuda_fp16.h>
#include <cstdint>
#include <cstddef>

// ----------------------------------------------------------------------------
// out[16384,4096] = spike[16384,4096] @ W[4096,4096] + bias   (fp32 I/O)
// FINAL — R10 core (verified optimum, 1337.9-1341.4 us across 3 runs):
//   cvt: fp32->fp16 merged pass at its DRAM roofline (~78 us).
//   GEMM: dense legacy mma.sync.m16n8k16 at ~95% of the rt~8 issue floor
//   (tensor 77.6% busy). BM=BN=128, BK=64, 3-stage cp.async, 2 CTAs/SM,
//   refill spread across kc, N-fastest CTA order, .cs streaming stores.
// This round: bias/output-address prefetch hoisted above the mainloop
// (removes one exposed L2 round-trip per CTA at the epilogue). Mainloop
// byte-identical to R10.
// ----------------------------------------------------------------------------

static constexpr int MM = 16384, KK = 4096, NN = 4096;
static constexpr int BM = 128, BN = 128, BK = 64;
static constexpr int STAGES = 3;
static constexpr int KTILES = KK / BK;           // 64
static constexpr int A_ST = BM * BK * 2;         // 16 KB (128B rows)
static constexpr int B_ST = BK * BN * 2;         // 16 KB (256B rows)
static constexpr int STG  = A_ST + B_ST;         // 32 KB
static constexpr int SMEM_BYTES = STAGES * STG;  // 96 KB -> 2 CTAs/SM

__device__ __align__(128) __half g_S[(size_t)MM * KK];   // 128 MB fp16 spikes
__device__ __align__(128) __half g_W[(size_t)KK * NN];   //  32 MB fp16 W [K,N]

// ---------------------------------------------------------------- helpers
__device__ __forceinline__ uint32_t smem_u32(const void* p) {
    uint32_t a;
    asm("{ .reg .u64 t; cvta.to.shared.u64 t, %1; cvt.u32.u64 %0, t; }"
        : "=r"(a) : "l"(p));
    return a;
}
__device__ __forceinline__ void cp16(uint32_t dst, const void* src) {
    asm volatile("cp.async.cg.shared.global [%0], [%1], 16;"
                 :: "r"(dst), "l"(src) : "memory");
}
__device__ __forceinline__ void st_cs_v2(float* p, float x, float y) {
    asm volatile("st.global.cs.v2.f32 [%0], {%1, %2};" :: "l"(p), "f"(x), "f"(y) : "memory");
}
__device__ __forceinline__ uint32_t swzA(uint32_t off) { return off ^ ((off >> 3) & 0x70); }
__device__ __forceinline__ uint32_t swzB(uint32_t off) { return off ^ ((off >> 4) & 0x70); }

#define LDSM4(R, addr)                                                          \
    asm volatile("ldmatrix.sync.aligned.m8n8.x4.shared.b16 {%0,%1,%2,%3}, [%4];"\
                 : "=r"((R)[0]), "=r"((R)[1]), "=r"((R)[2]), "=r"((R)[3])       \
                 : "r"(addr))
#define LDSM4T(R, addr)                                                         \
    asm volatile("ldmatrix.sync.aligned.m8n8.x4.trans.shared.b16 {%0,%1,%2,%3}, [%4];" \
                 : "=r"((R)[0]), "=r"((R)[1]), "=r"((R)[2]), "=r"((R)[3])       \
                 : "r"(addr))
#define MMA16816(C, A, B)                                                       \
    asm volatile("mma.sync.aligned.m16n8k16.row.col.f32.f16.f16.f32 "           \
                 "{%0,%1,%2,%3}, {%4,%5,%6,%7}, {%8,%9}, {%0,%1,%2,%3};"        \
                 : "+f"((C)[0]), "+f"((C)[1]), "+f"((C)[2]), "+f"((C)[3])       \
                 : "r"((A)[0]), "r"((A)[1]), "r"((A)[2]), "r"((A)[3]),          \
                   "r"((B)[0]), "r"((B)[1]))

// ---------------------------------------------------------------- merged cvt
__global__ void cvt_all(const float4* __restrict__ s_src, const float4* __restrict__ w_src) {
    const size_t stride = (size_t)gridDim.x * blockDim.x;
    const size_t tid0 = (size_t)blockIdx.x * blockDim.x + threadIdx.x;
    uint2* sdst = reinterpret_cast<uint2*>(g_S);
    uint2* wdst = reinterpret_cast<uint2*>(g_W);
    const size_t nS = (size_t)MM * KK / 4;
    const size_t nW = (size_t)KK * NN / 4;
    for (size_t i = tid0; i < nS; i += stride) {
        float4 v = __ldg(s_src + i);
        __half2 a = __floats2half2_rn(v.x, v.y);
        __half2 b = __floats2half2_rn(v.z, v.w);
        uint2 p;
        p.x = *reinterpret_cast<uint32_t*>(&a);
        p.y = *reinterpret_cast<uint32_t*>(&b);
        asm volatile("st.global.cs.v2.b32 [%0], {%1, %2};"
                     :: "l"(sdst + i), "r"(p.x), "r"(p.y) : "memory");
    }
    for (size_t i = tid0; i < nW; i += stride) {
        float4 v = __ldg(w_src + i);
        __half2 a = __floats2half2_rn(v.x, v.y);
        __half2 b = __floats2half2_rn(v.z, v.w);
        uint2 p;
        p.x = *reinterpret_cast<uint32_t*>(&a);
        p.y = *reinterpret_cast<uint32_t*>(&b);
        wdst[i] = p;
    }
}

// ---------------------------------------------------------------- GEMM
__global__ void __launch_bounds__(256, 2)
gemm_hmma_kernel(const float* __restrict__ bias, float* __restrict__ out) {
    extern __shared__ __align__(1024) unsigned char smem[];
    const uint32_t sb = smem_u32(smem);

    const int tid = threadIdx.x;
    const int lane = tid & 31;
    const int wid = tid >> 5;
    const int wm = wid >> 2;            // 0..1 : M half (64 rows)
    const int wn = wid & 3;             // 0..3 : N quarter (32 cols)
    const int tile_n = blockIdx.x & 31; // N fastest -> W stays L2-resident
    const int tile_m = blockIdx.x >> 5;

    const __half* Ab = g_S + (size_t)(tile_m * BM) * KK;
    const __half* Bb = g_W + tile_n * BN;

    const int arow = tid >> 3, acol = tid & 7;
    const int brow = tid >> 4, bcol = tid & 15;

    auto load_q = [&](int s, int t, int q) {
        const uint32_t sA = sb + s * STG;
        const int r = arow + q * 32;
        cp16(sA + swzA((uint32_t)(r * 128 + acol * 16)),
             Ab + (size_t)r * KK + t * BK + acol * 8);
        const uint32_t sB = sA + A_ST;
        const int rb = brow + q * 16;
        cp16(sB + swzB((uint32_t)(rb * 256 + bcol * 16)),
             Bb + (size_t)(t * BK + rb) * NN + bcol * 8);
    };
    auto load_tile = [&](int s, int t) {
#pragma unroll
        for (int q = 0; q < 4; q++) load_q(s, t, q);
    };

    // -------- prologue: fill pipeline + prefetch epilogue operands
#pragma unroll
    for (int s = 0; s < STAGES - 1; s++) {
        load_tile(s, s);
        asm volatile("cp.async.commit_group;");
    }

    // bias fragments + output base (hoisted: L2 latency absorbed by mainloop)
    float2 bv[4];
#pragma unroll
    for (int jj = 0; jj < 4; jj++)
        bv[jj] = __ldg(reinterpret_cast<const float2*>(
            bias + tile_n * BN + wn * 32 + jj * 8 + (lane & 3) * 2));
    float* const obase = out + (size_t)(tile_m * BM + wm * 64 + (lane >> 2)) * NN
                             + tile_n * BN + wn * 32 + (lane & 3) * 2;

    float acc[4][4][4];
#pragma unroll
    for (int i = 0; i < 4; i++)
#pragma unroll
        for (int j = 0; j < 4; j++)
#pragma unroll
            for (int q = 0; q < 4; q++) acc[i][j][q] = 0.0f;

#pragma unroll 1
    for (int tb = 0; tb < KTILES; tb += STAGES) {
#pragma unroll
        for (int ts = 0; ts < STAGES; ts++) {            // stage index == ts (immediates)
            const int t = tb + ts;
            if (t >= KTILES) break;
            asm volatile("cp.async.wait_group %0;" :: "n"(STAGES - 2));
            __syncthreads();

            const uint32_t sA = sb + ts * STG;
            const uint32_t sB = sA + A_ST;
            const int tn = t + STAGES - 1;
            const int sn = tn % STAGES;
            const bool do_refill = (tn < KTILES);

#pragma unroll
            for (int kc = 0; kc < 4; kc++) {
                if (do_refill) load_q(sn, tn, kc);       // spread refill

                uint32_t a[4][4];
#pragma unroll
                for (int i = 0; i < 4; i++) {
                    const int row = wm * 64 + i * 16 + (lane & 15);
                    LDSM4(a[i], sA + swzA((uint32_t)(row * 128 + (kc * 2 + (lane >> 4)) * 16)));
                }
                uint32_t b[2][4];
#pragma unroll
                for (int j = 0; j < 2; j++) {
                    const int krow = kc * 16 + (lane & 15);
                    const int colb = (wn * 32 + j * 16 + (lane >> 4) * 8) * 2;
                    LDSM4T(b[j], sB + swzB((uint32_t)(krow * 256 + colb)));
                }
#pragma unroll
                for (int i = 0; i < 4; i++)
#pragma unroll
                    for (int jj = 0; jj < 4; jj++)
                        MMA16816(acc[i][jj], a[i], b[jj >> 1] + (jj & 1) * 2);
            }
            asm volatile("cp.async.commit_group;");
        }
    }
    asm volatile("cp.async.wait_all;");

    // -------- epilogue: bias + streaming fp32 stores (evict-first)
#pragma unroll
    for (int i = 0; i < 4; i++) {
        float* o0 = obase + (size_t)(i * 16) * NN;
        float* o1 = o0 + (size_t)8 * NN;
#pragma unroll
        for (int jj = 0; jj < 4; jj++) {
            st_cs_v2(o0 + jj * 8, acc[i][jj][0] + bv[jj].x, acc[i][jj][1] + bv[jj].y);
            st_cs_v2(o1 + jj * 8, acc[i][jj][2] + bv[jj].x, acc[i][jj][3] + bv[jj].y);
        }
    }
}

// ---------------------------------------------------------------- launch
extern "C" void kernel_launch(void* const* d_in, const int* in_sizes, int n_in,
                              void* d_out, int out_size) {
    const float* sparse = (const float*)d_in[0];
    const float* weight = (const float*)d_in[1];
    const float* bias   = (const float*)d_in[2];
    float* out = (float*)d_out;

    cudaFuncSetAttribute(gemm_hmma_kernel,
                         cudaFuncAttributeMaxDynamicSharedMemorySize, SMEM_BYTES);

    cvt_all<<<4096, 256>>>(reinterpret_cast<const float4*>(sparse),
                           reinterpret_cast<const float4*>(weight));
    gemm_hmma_kernel<<<(MM / BM) * (NN / BN), 256, SMEM_BYTES>>>(bias, out);
}

// round 17
// speedup vs baseline: 1.0290x; 1.0290x over previous
#include <cuda_runtime.h>
#include <cuda_fp16.h>
#include <cstdint>
#include <cstddef>

// ----------------------------------------------------------------------------
// out[16384,4096] = spike[16384,4096] @ W[4096,4096] + bias   (fp32 I/O)
// FINAL — R10 configuration byte-identical (measured 1337.9 / 1340.5 us):
//   cvt_all: merged fp32->fp16 pass at its DRAM roofline (~78 us); spike
//   values {0,1} are exact in fp16, W quantization gives rel_err 1.84e-4.
//   gemm: dense legacy mma.sync.m16n8k16 at ~95% of the rt~8 issue floor
//   (tensor 77.7% busy). BM=BN=128, BK=64, 3-stage cp.async pipeline,
//   2 CTAs/SM, refill spread across kc, N-fastest CTA order for W L2
//   residency, .cs streaming stores.
// Rejected by measurement: tcgen05 (sm_100 gate), mma.sp (emulated, 4.4x),
// bitmask-A (-22%), K-desync (-3.8%), B double-buffer (-3.3%), warp
// kc-phasing (-11.7%), epilogue-operand hoist (-3.0%), cvt grid 8192 (-0.3%).
// ----------------------------------------------------------------------------

static constexpr int MM = 16384, KK = 4096, NN = 4096;
static constexpr int BM = 128, BN = 128, BK = 64;
static constexpr int STAGES = 3;
static constexpr int KTILES = KK / BK;           // 64
static constexpr int A_ST = BM * BK * 2;         // 16 KB (128B rows)
static constexpr int B_ST = BK * BN * 2;         // 16 KB (256B rows)
static constexpr int STG  = A_ST + B_ST;         // 32 KB
static constexpr int SMEM_BYTES = STAGES * STG;  // 96 KB -> 2 CTAs/SM

__device__ __align__(128) __half g_S[(size_t)MM * KK];   // 128 MB fp16 spikes
__device__ __align__(128) __half g_W[(size_t)KK * NN];   //  32 MB fp16 W [K,N]

// ---------------------------------------------------------------- helpers
__device__ __forceinline__ uint32_t smem_u32(const void* p) {
    uint32_t a;
    asm("{ .reg .u64 t; cvta.to.shared.u64 t, %1; cvt.u32.u64 %0, t; }"
        : "=r"(a) : "l"(p));
    return a;
}
__device__ __forceinline__ void cp16(uint32_t dst, const void* src) {
    asm volatile("cp.async.cg.shared.global [%0], [%1], 16;"
                 :: "r"(dst), "l"(src) : "memory");
}
__device__ __forceinline__ void st_cs_v2(float* p, float x, float y) {
    asm volatile("st.global.cs.v2.f32 [%0], {%1, %2};" :: "l"(p), "f"(x), "f"(y) : "memory");
}
__device__ __forceinline__ uint32_t swzA(uint32_t off) { return off ^ ((off >> 3) & 0x70); }
__device__ __forceinline__ uint32_t swzB(uint32_t off) { return off ^ ((off >> 4) & 0x70); }

#define LDSM4(R, addr)                                                          \
    asm volatile("ldmatrix.sync.aligned.m8n8.x4.shared.b16 {%0,%1,%2,%3}, [%4];"\
                 : "=r"((R)[0]), "=r"((R)[1]), "=r"((R)[2]), "=r"((R)[3])       \
                 : "r"(addr))
#define LDSM4T(R, addr)                                                         \
    asm volatile("ldmatrix.sync.aligned.m8n8.x4.trans.shared.b16 {%0,%1,%2,%3}, [%4];" \
                 : "=r"((R)[0]), "=r"((R)[1]), "=r"((R)[2]), "=r"((R)[3])       \
                 : "r"(addr))
#define MMA16816(C, A, B)                                                       \
    asm volatile("mma.sync.aligned.m16n8k16.row.col.f32.f16.f16.f32 "           \
                 "{%0,%1,%2,%3}, {%4,%5,%6,%7}, {%8,%9}, {%0,%1,%2,%3};"        \
                 : "+f"((C)[0]), "+f"((C)[1]), "+f"((C)[2]), "+f"((C)[3])       \
                 : "r"((A)[0]), "r"((A)[1]), "r"((A)[2]), "r"((A)[3]),          \
                   "r"((B)[0]), "r"((B)[1]))

// ---------------------------------------------------------------- merged cvt
__global__ void cvt_all(const float4* __restrict__ s_src, const float4* __restrict__ w_src) {
    const size_t stride = (size_t)gridDim.x * blockDim.x;
    const size_t tid0 = (size_t)blockIdx.x * blockDim.x + threadIdx.x;
    uint2* sdst = reinterpret_cast<uint2*>(g_S);
    uint2* wdst = reinterpret_cast<uint2*>(g_W);
    const size_t nS = (size_t)MM * KK / 4;
    const size_t nW = (size_t)KK * NN / 4;
    for (size_t i = tid0; i < nS; i += stride) {
        float4 v = __ldg(s_src + i);
        __half2 a = __floats2half2_rn(v.x, v.y);
        __half2 b = __floats2half2_rn(v.z, v.w);
        uint2 p;
        p.x = *reinterpret_cast<uint32_t*>(&a);
        p.y = *reinterpret_cast<uint32_t*>(&b);
        asm volatile("st.global.cs.v2.b32 [%0], {%1, %2};"
                     :: "l"(sdst + i), "r"(p.x), "r"(p.y) : "memory");
    }
    for (size_t i = tid0; i < nW; i += stride) {
        float4 v = __ldg(w_src + i);
        __half2 a = __floats2half2_rn(v.x, v.y);
        __half2 b = __floats2half2_rn(v.z, v.w);
        uint2 p;
        p.x = *reinterpret_cast<uint32_t*>(&a);
        p.y = *reinterpret_cast<uint32_t*>(&b);
        wdst[i] = p;
    }
}

// ---------------------------------------------------------------- GEMM
__global__ void __launch_bounds__(256, 2)
gemm_hmma_kernel(const float* __restrict__ bias, float* __restrict__ out) {
    extern __shared__ __align__(1024) unsigned char smem[];
    const uint32_t sb = smem_u32(smem);

    const int tid = threadIdx.x;
    const int lane = tid & 31;
    const int wid = tid >> 5;
    const int wm = wid >> 2;            // 0..1 : M half (64 rows)
    const int wn = wid & 3;             // 0..3 : N quarter (32 cols)
    const int tile_n = blockIdx.x & 31; // N fastest -> W stays L2-resident
    const int tile_m = blockIdx.x >> 5;

    const __half* Ab = g_S + (size_t)(tile_m * BM) * KK;
    const __half* Bb = g_W + tile_n * BN;

    const int arow = tid >> 3, acol = tid & 7;
    const int brow = tid >> 4, bcol = tid & 15;

    auto load_q = [&](int s, int t, int q) {
        const uint32_t sA = sb + s * STG;
        const int r = arow + q * 32;
        cp16(sA + swzA((uint32_t)(r * 128 + acol * 16)),
             Ab + (size_t)r * KK + t * BK + acol * 8);
        const uint32_t sB = sA + A_ST;
        const int rb = brow + q * 16;
        cp16(sB + swzB((uint32_t)(rb * 256 + bcol * 16)),
             Bb + (size_t)(t * BK + rb) * NN + bcol * 8);
    };
    auto load_tile = [&](int s, int t) {
#pragma unroll
        for (int q = 0; q < 4; q++) load_q(s, t, q);
    };

    // -------- prologue
#pragma unroll
    for (int s = 0; s < STAGES - 1; s++) {
        load_tile(s, s);
        asm volatile("cp.async.commit_group;");
    }

    float acc[4][4][4];
#pragma unroll
    for (int i = 0; i < 4; i++)
#pragma unroll
        for (int j = 0; j < 4; j++)
#pragma unroll
            for (int q = 0; q < 4; q++) acc[i][j][q] = 0.0f;

#pragma unroll 1
    for (int tb = 0; tb < KTILES; tb += STAGES) {
#pragma unroll
        for (int ts = 0; ts < STAGES; ts++) {            // stage index == ts (immediates)
            const int t = tb + ts;
            if (t >= KTILES) break;
            asm volatile("cp.async.wait_group %0;" :: "n"(STAGES - 2));
            __syncthreads();

            const uint32_t sA = sb + ts * STG;
            const uint32_t sB = sA + A_ST;
            const int tn = t + STAGES - 1;
            const int sn = tn % STAGES;
            const bool do_refill = (tn < KTILES);

#pragma unroll
            for (int kc = 0; kc < 4; kc++) {
                if (do_refill) load_q(sn, tn, kc);       // spread refill

                uint32_t a[4][4];
#pragma unroll
                for (int i = 0; i < 4; i++) {
                    const int row = wm * 64 + i * 16 + (lane & 15);
                    LDSM4(a[i], sA + swzA((uint32_t)(row * 128 + (kc * 2 + (lane >> 4)) * 16)));
                }
                uint32_t b[2][4];
#pragma unroll
                for (int j = 0; j < 2; j++) {
                    const int krow = kc * 16 + (lane & 15);
                    const int colb = (wn * 32 + j * 16 + (lane >> 4) * 8) * 2;
                    LDSM4T(b[j], sB + swzB((uint32_t)(krow * 256 + colb)));
                }
#pragma unroll
                for (int i = 0; i < 4; i++)
#pragma unroll
                    for (int jj = 0; jj < 4; jj++)
                        MMA16816(acc[i][jj], a[i], b[jj >> 1] + (jj & 1) * 2);
            }
            asm volatile("cp.async.commit_group;");
        }
    }
    asm volatile("cp.async.wait_all;");

    // -------- epilogue: bias + streaming fp32 stores (evict-first)
    float2 bv[4];
#pragma unroll
    for (int jj = 0; jj < 4; jj++)
        bv[jj] = *reinterpret_cast<const float2*>(
            bias + tile_n * BN + wn * 32 + jj * 8 + (lane & 3) * 2);

#pragma unroll
    for (int i = 0; i < 4; i++) {
        const int r = tile_m * BM + wm * 64 + i * 16 + (lane >> 2);
        float* o0 = out + (size_t)r * NN + tile_n * BN + wn * 32 + (lane & 3) * 2;
        float* o1 = o0 + (size_t)8 * NN;
#pragma unroll
        for (int jj = 0; jj < 4; jj++) {
            st_cs_v2(o0 + jj * 8, acc[i][jj][0] + bv[jj].x, acc[i][jj][1] + bv[jj].y);
            st_cs_v2(o1 + jj * 8, acc[i][jj][2] + bv[jj].x, acc[i][jj][3] + bv[jj].y);
        }
    }
}

// ---------------------------------------------------------------- launch
extern "C" void kernel_launch(void* const* d_in, const int* in_sizes, int n_in,
                              void* d_out, int out_size) {
    const float* sparse = (const float*)d_in[0];
    const float* weight = (const float*)d_in[1];
    const float* bias   = (const float*)d_in[2];
    float* out = (float*)d_out;

    cudaFuncSetAttribute(gemm_hmma_kernel,
                         cudaFuncAttributeMaxDynamicSharedMemorySize, SMEM_BYTES);

    cvt_all<<<4096, 256>>>(reinterpret_cast<const float4*>(sparse),
                           reinterpret_cast<const float4*>(weight));
    gemm_hmma_kernel<<<(MM / BM) * (NN / BN), 256, SMEM_BYTES>>>(bias, out);
}